// round 10
// baseline (speedup 1.0000x reference)
#include <cuda_runtime.h>
#include <cuda_fp16.h>
#include <cstdint>

#define NODES_MAX 100000
#define NPER 12
#define ROWH 16   // padded fp16 row: 16 halves = 32 B = one L2 sector

__device__ int    g_deg[NODES_MAX];          // zero-init at load; k_final re-zeroes each call
__device__ float  g_dinv[NODES_MAX];
__device__ __align__(32) __half g_yh[NODES_MAX * ROWH];    // y = x * dinv_src, fp16
__device__ __align__(32) __half g_acch[NODES_MAX * ROWH];  // fp16 accumulator (seeded with y = self loop)
// folded coefficients: azh[4] (=az/2), bzh[4] (=bz/2), ah[4], bh[4], wh[12] (=softmax/2)
__device__ float g_cf[32];

// ---------------- K1: degree count (8 edges/thread) + coef fold ----------------
__global__ void k_deg(const int* __restrict__ dst, int E,
                      const float* __restrict__ cz_w, const float* __restrict__ cz_b,
                      const float* __restrict__ lz_w, const float* __restrict__ lz_b,
                      const float* __restrict__ ch_w, const float* __restrict__ ch_b,
                      const float* __restrict__ lh_w, const float* __restrict__ lh_b,
                      const float* __restrict__ att) {
    int i = blockIdx.x * blockDim.x + threadIdx.x;
    int e8 = E >> 3;
    if (i < e8) {
        int4 a = ((const int4*)dst)[2 * i];
        int4 b = ((const int4*)dst)[2 * i + 1];
        atomicAdd(&g_deg[a.x], 1);
        atomicAdd(&g_deg[a.y], 1);
        atomicAdd(&g_deg[a.z], 1);
        atomicAdd(&g_deg[a.w], 1);
        atomicAdd(&g_deg[b.x], 1);
        atomicAdd(&g_deg[b.y], 1);
        atomicAdd(&g_deg[b.z], 1);
        atomicAdd(&g_deg[b.w], 1);
    } else if (i == e8) {
        for (int r = e8 * 8; r < E; r++) atomicAdd(&g_deg[dst[r]], 1);
    }
    if (blockIdx.x == 0 && threadIdx.x == 0) {
        for (int c = 0; c < 4; c++) {
            float a = 0.f, b = lz_b[c];
            float a2 = 0.f, b2 = lh_b[c];
            for (int k = 0; k < 4; k++) {
                float lz = lz_w[k * 4 + c];
                float lh = lh_w[k * 4 + c];
                a  += cz_w[k] * lz;
                b  += cz_b[k] * lz;
                a2 += ch_w[k] * lh;
                b2 += ch_b[k] * lh;
            }
            g_cf[c]     = 0.5f * a;   // halved: sigmoid(x) = 0.5 + 0.5*tanh(x/2)
            g_cf[4 + c] = 0.5f * b;
            g_cf[8 + c]  = a2;
            g_cf[12 + c] = b2;
        }
        float m = -1e30f;
        for (int p = 0; p < NPER; p++) m = fmaxf(m, att[p]);
        float sum = 0.f;
        float e[NPER];
        for (int p = 0; p < NPER; p++) { e[p] = __expf(att[p] - m); sum += e[p]; }
        float inv = 0.5f / sum;  // absorbs the 0.5 from (1-z) = 0.5*(1-t1)
        for (int p = 0; p < NPER; p++) g_cf[16 + p] = e[p] * inv;
    }
}

// ---------------- K2: dinv + scaled x into fp16 rows; acc seeded with y (self loop) ----------------
__global__ void k_prep(const float* __restrict__ x, int n) {
    int i = blockIdx.x * blockDim.x + threadIdx.x;
    if (i >= n) return;
    float dinv = rsqrtf((float)(g_deg[i] + 1));  // +1 for self loop
    g_dinv[i] = dinv;
    const float4* xr = (const float4*)(x + (size_t)i * NPER);
    float4 a = xr[0], b = xr[1], c = xr[2];
    __half2 h0 = __floats2half2_rn(a.x * dinv, a.y * dinv);
    __half2 h1 = __floats2half2_rn(a.z * dinv, a.w * dinv);
    __half2 h2 = __floats2half2_rn(b.x * dinv, b.y * dinv);
    __half2 h3 = __floats2half2_rn(b.z * dinv, b.w * dinv);
    __half2 h4 = __floats2half2_rn(c.x * dinv, c.y * dinv);
    __half2 h5 = __floats2half2_rn(c.z * dinv, c.w * dinv);
    uint4 lo;
    lo.x = *(unsigned*)&h0;
    lo.y = *(unsigned*)&h1;
    lo.z = *(unsigned*)&h2;
    lo.w = *(unsigned*)&h3;
    uint4 hi;
    hi.x = *(unsigned*)&h4;
    hi.y = *(unsigned*)&h5;
    hi.z = 0;
    hi.w = 0;
    uint4* row = (uint4*)(g_yh + (size_t)i * ROWH);
    row[0] = lo;
    row[1] = hi;
    // seed accumulator with the self-loop message:
    // final s = dinv * (y_self + sum_edges y_src) = dinv^2*x + dinv*sum
    uint4* arow = (uint4*)(g_acch + (size_t)i * ROWH);
    arow[0] = lo;
    arow[1] = hi;
}

// ---------------- K3: edge scatter via TMA bulk-reduce, 4 edges/thread ----------------
__device__ __forceinline__ void scatter_one(int d, uint4 lo, uint2 hi) {
    __half* ap = g_acch + (size_t)d * ROWH;
    asm volatile("red.global.add.noftz.v4.f16x2 [%0], {%1,%2,%3,%4};"
                 :: "l"(ap), "r"(lo.x), "r"(lo.y), "r"(lo.z), "r"(lo.w)
                 : "memory");
    asm volatile("red.global.add.noftz.v2.f16x2 [%0], {%1,%2};"
                 :: "l"(ap + 8), "r"(hi.x), "r"(hi.y)
                 : "memory");
}

__global__ void k_scatter(const int* __restrict__ src, const int* __restrict__ dst, int E) {
    // 4 slots of 32B per thread, 256 threads -> 32KB static smem
    __shared__ __align__(32) unsigned sbuf[256 * 4 * 8];
    int t = blockIdx.x * blockDim.x + threadIdx.x;
    int e4 = E >> 2;
    // shared address (u32) of this thread's first slot
    unsigned sb;
    {
        unsigned* p = &sbuf[threadIdx.x * 32];  // 32 u32 = 128 B per thread
        asm("{ .reg .u64 tt; cvta.to.shared.u64 tt, %1; cvt.u32.u64 %0, tt; }"
            : "=r"(sb) : "l"(p));
    }
    if (t < e4) {
        int4 s4 = ((const int4*)src)[t];
        int4 d4 = ((const int4*)dst)[t];
        const uint4* y0 = (const uint4*)(g_yh + (size_t)s4.x * ROWH);
        const uint4* y1 = (const uint4*)(g_yh + (size_t)s4.y * ROWH);
        const uint4* y2 = (const uint4*)(g_yh + (size_t)s4.z * ROWH);
        const uint4* y3 = (const uint4*)(g_yh + (size_t)s4.w * ROWH);
        uint4 lo0 = __ldg(y0); uint2 hi0 = __ldg((const uint2*)(y0 + 1));
        uint4 lo1 = __ldg(y1); uint2 hi1 = __ldg((const uint2*)(y1 + 1));
        uint4 lo2 = __ldg(y2); uint2 hi2 = __ldg((const uint2*)(y2 + 1));
        uint4 lo3 = __ldg(y3); uint2 hi3 = __ldg((const uint2*)(y3 + 1));
        // stage rows in smem (pad words zero so the 32B bulk add is exact)
        asm volatile("st.shared.v4.b32 [%0], {%1,%2,%3,%4};" :: "r"(sb),
                     "r"(lo0.x), "r"(lo0.y), "r"(lo0.z), "r"(lo0.w));
        asm volatile("st.shared.v4.b32 [%0], {%1,%2,%3,%4};" :: "r"(sb + 16),
                     "r"(hi0.x), "r"(hi0.y), "r"(0u), "r"(0u));
        asm volatile("st.shared.v4.b32 [%0], {%1,%2,%3,%4};" :: "r"(sb + 32),
                     "r"(lo1.x), "r"(lo1.y), "r"(lo1.z), "r"(lo1.w));
        asm volatile("st.shared.v4.b32 [%0], {%1,%2,%3,%4};" :: "r"(sb + 48),
                     "r"(hi1.x), "r"(hi1.y), "r"(0u), "r"(0u));
        asm volatile("st.shared.v4.b32 [%0], {%1,%2,%3,%4};" :: "r"(sb + 64),
                     "r"(lo2.x), "r"(lo2.y), "r"(lo2.z), "r"(lo2.w));
        asm volatile("st.shared.v4.b32 [%0], {%1,%2,%3,%4};" :: "r"(sb + 80),
                     "r"(hi2.x), "r"(hi2.y), "r"(0u), "r"(0u));
        asm volatile("st.shared.v4.b32 [%0], {%1,%2,%3,%4};" :: "r"(sb + 96),
                     "r"(lo3.x), "r"(lo3.y), "r"(lo3.z), "r"(lo3.w));
        asm volatile("st.shared.v4.b32 [%0], {%1,%2,%3,%4};" :: "r"(sb + 112),
                     "r"(hi3.x), "r"(hi3.y), "r"(0u), "r"(0u));
        // order generic smem stores before async-proxy reads
        asm volatile("fence.proxy.async.shared::cta;" ::: "memory");
        const __half* a0 = g_acch + (size_t)d4.x * ROWH;
        const __half* a1 = g_acch + (size_t)d4.y * ROWH;
        const __half* a2 = g_acch + (size_t)d4.z * ROWH;
        const __half* a3 = g_acch + (size_t)d4.w * ROWH;
        asm volatile("cp.reduce.async.bulk.global.shared::cta.bulk_group.add.noftz.f16 [%0], [%1], 32;"
                     :: "l"(a0), "r"(sb) : "memory");
        asm volatile("cp.reduce.async.bulk.global.shared::cta.bulk_group.add.noftz.f16 [%0], [%1], 32;"
                     :: "l"(a1), "r"(sb + 32) : "memory");
        asm volatile("cp.reduce.async.bulk.global.shared::cta.bulk_group.add.noftz.f16 [%0], [%1], 32;"
                     :: "l"(a2), "r"(sb + 64) : "memory");
        asm volatile("cp.reduce.async.bulk.global.shared::cta.bulk_group.add.noftz.f16 [%0], [%1], 32;"
                     :: "l"(a3), "r"(sb + 96) : "memory");
        asm volatile("cp.async.bulk.commit_group;" ::: "memory");
        asm volatile("cp.async.bulk.wait_group 0;" ::: "memory");
    } else if (t == e4) {
        for (int r = e4 * 4; r < E; r++) {
            int s = src[r], d = dst[r];
            const uint4* yr = (const uint4*)(g_yh + (size_t)s * ROWH);
            uint4 lo = __ldg(yr); uint2 hi = __ldg((const uint2*)(yr + 1));
            scatter_one(d, lo, hi);
        }
    }
}

// ---------------- K4: per-node epilogue (+ re-zero deg for next call) ----------------
__device__ __forceinline__ float tanh_fast(float x) {
    float y;
    asm("tanh.approx.f32 %0, %1;" : "=f"(y) : "f"(x));
    return y;
}

__global__ void k_final(const float* __restrict__ ow, const float* __restrict__ ob,
                        float* __restrict__ out, int n) {
    int i = blockIdx.x * blockDim.x + threadIdx.x;
    if (i >= n) return;

    g_deg[i] = 0;  // leave deg zeroed for the next kernel_launch call

    float azh[4], bzh[4], ah[4], bh[4], wh[NPER];
#pragma unroll
    for (int c = 0; c < 4; c++) {
        azh[c] = __ldg(&g_cf[c]);
        bzh[c] = __ldg(&g_cf[4 + c]);
        ah[c]  = __ldg(&g_cf[8 + c]);
        bh[c]  = __ldg(&g_cf[12 + c]);
    }
#pragma unroll
    for (int p = 0; p < NPER; p++) wh[p] = __ldg(&g_cf[16 + p]);

    float dinv = g_dinv[i];

    const uint4* ar = (const uint4*)(g_acch + (size_t)i * ROWH);
    uint4 alo = ar[0];
    uint2 ahi = *(const uint2*)(ar + 1);
    float av[NPER];
    {
        float2 t;
        t = __half22float2(*(__half2*)&alo.x); av[0] = t.x; av[1] = t.y;
        t = __half22float2(*(__half2*)&alo.y); av[2] = t.x; av[3] = t.y;
        t = __half22float2(*(__half2*)&alo.z); av[4] = t.x; av[5] = t.y;
        t = __half22float2(*(__half2*)&alo.w); av[6] = t.x; av[7] = t.y;
        t = __half22float2(*(__half2*)&ahi.x); av[8] = t.x; av[9] = t.y;
        t = __half22float2(*(__half2*)&ahi.y); av[10] = t.x; av[11] = t.y;
    }

    float H[4] = {0.f, 0.f, 0.f, 0.f};
#pragma unroll
    for (int p = 0; p < NPER; p++) {
        float sp = dinv * av[p];   // acc already includes self-loop message
        float w = wh[p];           // = softmax_p / 2
#pragma unroll
        for (int c = 0; c < 4; c++) {
            float t1 = tanh_fast(fmaf(sp, azh[c], bzh[c]));
            float t2 = tanh_fast(fmaf(sp, ah[c], bh[c]));
            H[c] = fmaf(w * (1.0f - t1), t2, H[c]);
        }
    }

    float o[NPER];
#pragma unroll
    for (int f = 0; f < NPER; f++) {
        float v = __ldg(&ob[f]);
#pragma unroll
        for (int c = 0; c < 4; c++) v = fmaf(H[c], __ldg(&ow[c * NPER + f]), v);
        o[f] = v;
    }
    float4* orow = (float4*)(out + (size_t)i * NPER);
    orow[0] = make_float4(o[0], o[1], o[2], o[3]);
    orow[1] = make_float4(o[4], o[5], o[6], o[7]);
    orow[2] = make_float4(o[8], o[9], o[10], o[11]);
}

// ---------------- launch ----------------
extern "C" void kernel_launch(void* const* d_in, const int* in_sizes, int n_in,
                              void* d_out, int out_size) {
    const float* x  = (const float*)d_in[0];
    const int*   ei = (const int*)d_in[1];
    const float* cz_w = (const float*)d_in[2];
    const float* cz_b = (const float*)d_in[3];
    const float* lz_w = (const float*)d_in[4];
    const float* lz_b = (const float*)d_in[5];
    // d_in[6..9] = conv_r / lin_r : dead (multiplied by H0 == 0)
    const float* ch_w = (const float*)d_in[10];
    const float* ch_b = (const float*)d_in[11];
    const float* lh_w = (const float*)d_in[12];
    const float* lh_b = (const float*)d_in[13];
    const float* att  = (const float*)d_in[14];
    const float* ow   = (const float*)d_in[15];
    const float* ob   = (const float*)d_in[16];
    float* out = (float*)d_out;

    int N = in_sizes[0] / NPER;
    int E = in_sizes[1] / 2;
    const int* src = ei;
    const int* dst = ei + E;

    const int TB = 256;
    int q8 = (E >> 3) + 1;
    int q4 = (E >> 2) + 1;
    k_deg<<<(q8 + TB - 1) / TB, TB>>>(dst, E, cz_w, cz_b, lz_w, lz_b,
                                      ch_w, ch_b, lh_w, lh_b, att);
    k_prep<<<(N + TB - 1) / TB, TB>>>(x, N);
    k_scatter<<<(q4 + TB - 1) / TB, TB>>>(src, dst, E);
    k_final<<<(N + TB - 1) / TB, TB>>>(ow, ob, out, N);
}

// round 11
// speedup vs baseline: 1.3656x; 1.3656x over previous
#include <cuda_runtime.h>
#include <cuda_fp16.h>
#include <cstdint>

#define NODES_MAX 100000
#define NPER 12
#define ROWH 16   // padded fp16 row: 16 halves = 32 B = one L2 sector

__device__ int    g_deg[NODES_MAX];          // zero-init at load; k_final re-zeroes each call
__device__ float  g_dinv[NODES_MAX];
__device__ __align__(32) __half g_yh[NODES_MAX * ROWH];    // y = x * dinv_src, fp16 (last 4 halves zero)
__device__ __align__(32) __half g_acch[NODES_MAX * ROWH];  // fp16 accumulator (seeded with y = self loop)
// folded coefficients: azh[4] (=az/2), bzh[4] (=bz/2), ah[4], bh[4], wh[12] (=softmax/2)
__device__ float g_cf[32];

// ---------------- K1: degree count (8 edges/thread) + coef fold ----------------
__global__ void k_deg(const int* __restrict__ dst, int E,
                      const float* __restrict__ cz_w, const float* __restrict__ cz_b,
                      const float* __restrict__ lz_w, const float* __restrict__ lz_b,
                      const float* __restrict__ ch_w, const float* __restrict__ ch_b,
                      const float* __restrict__ lh_w, const float* __restrict__ lh_b,
                      const float* __restrict__ att) {
    int i = blockIdx.x * blockDim.x + threadIdx.x;
    int e8 = E >> 3;
    if (i < e8) {
        int4 a = ((const int4*)dst)[2 * i];
        int4 b = ((const int4*)dst)[2 * i + 1];
        atomicAdd(&g_deg[a.x], 1);
        atomicAdd(&g_deg[a.y], 1);
        atomicAdd(&g_deg[a.z], 1);
        atomicAdd(&g_deg[a.w], 1);
        atomicAdd(&g_deg[b.x], 1);
        atomicAdd(&g_deg[b.y], 1);
        atomicAdd(&g_deg[b.z], 1);
        atomicAdd(&g_deg[b.w], 1);
    } else if (i == e8) {
        for (int r = e8 * 8; r < E; r++) atomicAdd(&g_deg[dst[r]], 1);
    }
    if (blockIdx.x == 0 && threadIdx.x == 0) {
        for (int c = 0; c < 4; c++) {
            float a = 0.f, b = lz_b[c];
            float a2 = 0.f, b2 = lh_b[c];
            for (int k = 0; k < 4; k++) {
                float lz = lz_w[k * 4 + c];
                float lh = lh_w[k * 4 + c];
                a  += cz_w[k] * lz;
                b  += cz_b[k] * lz;
                a2 += ch_w[k] * lh;
                b2 += ch_b[k] * lh;
            }
            g_cf[c]     = 0.5f * a;   // halved: sigmoid(x) = 0.5 + 0.5*tanh(x/2)
            g_cf[4 + c] = 0.5f * b;
            g_cf[8 + c]  = a2;
            g_cf[12 + c] = b2;
        }
        float m = -1e30f;
        for (int p = 0; p < NPER; p++) m = fmaxf(m, att[p]);
        float sum = 0.f;
        float e[NPER];
        for (int p = 0; p < NPER; p++) { e[p] = __expf(att[p] - m); sum += e[p]; }
        float inv = 0.5f / sum;  // absorbs the 0.5 from (1-z) = 0.5*(1-t1)
        for (int p = 0; p < NPER; p++) g_cf[16 + p] = e[p] * inv;
    }
}

// ---------------- K2: dinv + scaled x into fp16 rows; acc seeded with y (self loop) ----------------
__global__ void k_prep(const float* __restrict__ x, int n) {
    int i = blockIdx.x * blockDim.x + threadIdx.x;
    if (i >= n) return;
    float dinv = rsqrtf((float)(g_deg[i] + 1));  // +1 for self loop
    g_dinv[i] = dinv;
    const float4* xr = (const float4*)(x + (size_t)i * NPER);
    float4 a = xr[0], b = xr[1], c = xr[2];
    __half2 h0 = __floats2half2_rn(a.x * dinv, a.y * dinv);
    __half2 h1 = __floats2half2_rn(a.z * dinv, a.w * dinv);
    __half2 h2 = __floats2half2_rn(b.x * dinv, b.y * dinv);
    __half2 h3 = __floats2half2_rn(b.z * dinv, b.w * dinv);
    __half2 h4 = __floats2half2_rn(c.x * dinv, c.y * dinv);
    __half2 h5 = __floats2half2_rn(c.z * dinv, c.w * dinv);
    uint4 lo;
    lo.x = *(unsigned*)&h0;
    lo.y = *(unsigned*)&h1;
    lo.z = *(unsigned*)&h2;
    lo.w = *(unsigned*)&h3;
    uint4 hi;
    hi.x = *(unsigned*)&h4;
    hi.y = *(unsigned*)&h5;
    hi.z = 0;
    hi.w = 0;
    uint4* row = (uint4*)(g_yh + (size_t)i * ROWH);
    row[0] = lo;
    row[1] = hi;
    // seed accumulator with the self-loop message:
    // final s = dinv * (y_self + sum_edges y_src) = dinv^2*x + dinv*sum
    uint4* arow = (uint4*)(g_acch + (size_t)i * ROWH);
    arow[0] = lo;
    arow[1] = hi;
}

// ---------------- K3: edge scatter, 2 lanes per edge (half-row tasks) ----------------
// task u (0..2E): edge e = u>>1, half h = u&1. Even/odd lanes handle the two
// 16B halves of a row, so gather is ONE LDG.128 per edge-pair-instruction and
// the reduction ONE red.v4.f16x2 (adding zeros into the 4 pad halves is a no-op).
__global__ void k_scatter(const int* __restrict__ src, const int* __restrict__ dst, int E) {
    int T = 2 * E;
    int stride = blockDim.x * gridDim.x;
    int u = blockIdx.x * blockDim.x + threadIdx.x;
#pragma unroll 4
    for (int k = 0; k < 4; k++) {
        int task = u + k * stride;
        if (task < T) {
            int e = task >> 1;
            int h = task & 1;
            int s = __ldg(&src[e]);
            int d = __ldg(&dst[e]);
            const uint4* yp = (const uint4*)(g_yh + (size_t)s * ROWH) + h;
            uint4 v = __ldg(yp);
            __half* ap = g_acch + (size_t)d * ROWH + h * 8;
            asm volatile("red.global.add.noftz.v4.f16x2 [%0], {%1,%2,%3,%4};"
                         :: "l"(ap), "r"(v.x), "r"(v.y), "r"(v.z), "r"(v.w)
                         : "memory");
        }
    }
}

// ---------------- K4: per-node epilogue (+ re-zero deg for next call) ----------------
__device__ __forceinline__ float tanh_fast(float x) {
    float y;
    asm("tanh.approx.f32 %0, %1;" : "=f"(y) : "f"(x));
    return y;
}

__global__ void k_final(const float* __restrict__ ow, const float* __restrict__ ob,
                        float* __restrict__ out, int n) {
    int i = blockIdx.x * blockDim.x + threadIdx.x;
    if (i >= n) return;

    g_deg[i] = 0;  // leave deg zeroed for the next kernel_launch call

    float azh[4], bzh[4], ah[4], bh[4], wh[NPER];
#pragma unroll
    for (int c = 0; c < 4; c++) {
        azh[c] = __ldg(&g_cf[c]);
        bzh[c] = __ldg(&g_cf[4 + c]);
        ah[c]  = __ldg(&g_cf[8 + c]);
        bh[c]  = __ldg(&g_cf[12 + c]);
    }
#pragma unroll
    for (int p = 0; p < NPER; p++) wh[p] = __ldg(&g_cf[16 + p]);

    float dinv = g_dinv[i];

    const uint4* ar = (const uint4*)(g_acch + (size_t)i * ROWH);
    uint4 alo = ar[0];
    uint2 ahi = *(const uint2*)(ar + 1);
    float av[NPER];
    {
        float2 t;
        t = __half22float2(*(__half2*)&alo.x); av[0] = t.x; av[1] = t.y;
        t = __half22float2(*(__half2*)&alo.y); av[2] = t.x; av[3] = t.y;
        t = __half22float2(*(__half2*)&alo.z); av[4] = t.x; av[5] = t.y;
        t = __half22float2(*(__half2*)&alo.w); av[6] = t.x; av[7] = t.y;
        t = __half22float2(*(__half2*)&ahi.x); av[8] = t.x; av[9] = t.y;
        t = __half22float2(*(__half2*)&ahi.y); av[10] = t.x; av[11] = t.y;
    }

    float H[4] = {0.f, 0.f, 0.f, 0.f};
#pragma unroll
    for (int p = 0; p < NPER; p++) {
        float sp = dinv * av[p];   // acc already includes self-loop message
        float w = wh[p];           // = softmax_p / 2
#pragma unroll
        for (int c = 0; c < 4; c++) {
            float t1 = tanh_fast(fmaf(sp, azh[c], bzh[c]));
            float t2 = tanh_fast(fmaf(sp, ah[c], bh[c]));
            H[c] = fmaf(w * (1.0f - t1), t2, H[c]);
        }
    }

    float o[NPER];
#pragma unroll
    for (int f = 0; f < NPER; f++) {
        float v = __ldg(&ob[f]);
#pragma unroll
        for (int c = 0; c < 4; c++) v = fmaf(H[c], __ldg(&ow[c * NPER + f]), v);
        o[f] = v;
    }
    float4* orow = (float4*)(out + (size_t)i * NPER);
    orow[0] = make_float4(o[0], o[1], o[2], o[3]);
    orow[1] = make_float4(o[4], o[5], o[6], o[7]);
    orow[2] = make_float4(o[8], o[9], o[10], o[11]);
}

// ---------------- launch ----------------
extern "C" void kernel_launch(void* const* d_in, const int* in_sizes, int n_in,
                              void* d_out, int out_size) {
    const float* x  = (const float*)d_in[0];
    const int*   ei = (const int*)d_in[1];
    const float* cz_w = (const float*)d_in[2];
    const float* cz_b = (const float*)d_in[3];
    const float* lz_w = (const float*)d_in[4];
    const float* lz_b = (const float*)d_in[5];
    // d_in[6..9] = conv_r / lin_r : dead (multiplied by H0 == 0)
    const float* ch_w = (const float*)d_in[10];
    const float* ch_b = (const float*)d_in[11];
    const float* lh_w = (const float*)d_in[12];
    const float* lh_b = (const float*)d_in[13];
    const float* att  = (const float*)d_in[14];
    const float* ow   = (const float*)d_in[15];
    const float* ob   = (const float*)d_in[16];
    float* out = (float*)d_out;

    int N = in_sizes[0] / NPER;
    int E = in_sizes[1] / 2;
    const int* src = ei;
    const int* dst = ei + E;

    const int TB = 256;
    int q8 = (E >> 3) + 1;
    k_deg<<<(q8 + TB - 1) / TB, TB>>>(dst, E, cz_w, cz_b, lz_w, lz_b,
                                      ch_w, ch_b, lh_w, lh_b, att);
    k_prep<<<(N + TB - 1) / TB, TB>>>(x, N);
    // 2E tasks, 4 tasks per thread
    int T = 2 * E;
    int nthreads = (T + 3) / 4;
    k_scatter<<<(nthreads + TB - 1) / TB, TB>>>(src, dst, E);
    k_final<<<(N + TB - 1) / TB, TB>>>(ow, ob, out, N);
}